// round 4
// baseline (speedup 1.0000x reference)
#include <cuda_runtime.h>

// RNN: h_{s+1} = tanh(X[s]*W_ih^T + b_ih + b_hh + h_s @ W_hh^T); y_s = h_{s+1}·W_out + b_out
// SEQ=512, BATCH=4096, IN_DIM=1, HID=30.
//
// FMA-pipe-bound (1.89G fp32 MACs, ~16MB HBM total). Layout:
// - lane j (<30) holds W_hh row j replicated into f32x2 regs; lane 30 holds W_out,
//   so the Linear readout is produced by the same matvec loop (no reduction).
//   NOTE: lane 30's accumulator at iteration s equals y[s-1] (it consumes the
//   state ENTERING step s) -> store shifted, with one epilogue matvec for y[SEQ-1].
// - each warp owns 4 batch elements as 2 x f32x2 accumulators.
// - h state in warp-private smem float4[30]; one LDS.128 broadcast feeds 2 FFMA2.
// - tanh = 1 - 2/(ex2(2*log2e*x)+1) via ex2.approx+rcp.approx (~1e-6 rel err;
//   tanh.approx's 1e-3 would compound through the 512-step recurrence).

#define SEQ   512
#define BATCH 4096
#define HID   30

typedef unsigned long long u64;

__device__ __forceinline__ u64 pack2(float lo, float hi) {
    u64 r;
    asm("mov.b64 %0, {%1, %2};" : "=l"(r) : "f"(lo), "f"(hi));
    return r;
}
__device__ __forceinline__ void unpack2(u64 v, float& a, float& b) {
    asm("mov.b64 {%0, %1}, %2;" : "=f"(a), "=f"(b) : "l"(v));
}
__device__ __forceinline__ u64 fma2(u64 a, u64 b, u64 c) {
    u64 d;
    asm("fma.rn.f32x2 %0, %1, %2, %3;" : "=l"(d) : "l"(a), "l"(b), "l"(c));
    return d;
}

// tanh(x) = 1 - 2/(exp(2x)+1), exp via MUFU.EX2. Saturates correctly at +-1.
__device__ __forceinline__ float fast_tanh(float x) {
    float t, r;
    asm("ex2.approx.f32 %0, %1;" : "=f"(t) : "f"(x * 2.8853900817779268f)); // 2*log2(e)
    asm("rcp.approx.f32 %0, %1;" : "=f"(r) : "f"(t + 1.0f));
    return __fmaf_rn(-2.0f, r, 1.0f);
}

__global__ void __launch_bounds__(128) rnn_tanh_kernel(
    const float* __restrict__ X,      // [SEQ, BATCH, 1]
    const float* __restrict__ W_ih,   // [HID, 1]
    const float* __restrict__ W_hh,   // [HID, HID]
    const float* __restrict__ b_ih,   // [HID]
    const float* __restrict__ b_hh,   // [HID]
    const float* __restrict__ W_out,  // [1, HID]
    const float* __restrict__ b_out,  // [1]
    float* __restrict__ Y)            // [SEQ, BATCH, 1]
{
    __shared__ float4 hbuf[4][2][HID];

    const int lane = threadIdx.x & 31;
    const int wip  = threadIdx.x >> 5;
    const int gw   = blockIdx.x * 4 + wip;          // global warp id; batch base = 4*gw

    // Per-lane weight row, replicated into both f32x2 halves.
    u64 Wrep[HID];
    float wih = 0.0f, bias = 0.0f;
    if (lane < HID) {
        #pragma unroll
        for (int i = 0; i < HID; i++) {
            float w = W_hh[lane * HID + i];
            Wrep[i] = pack2(w, w);
        }
        wih  = W_ih[lane];
        bias = b_ih[lane] + b_hh[lane];
    } else if (lane == HID) {
        #pragma unroll
        for (int i = 0; i < HID; i++) {
            float w = W_out[i];
            Wrep[i] = pack2(w, w);
        }
        bias = b_out[0];
    } else {
        #pragma unroll
        for (int i = 0; i < HID; i++) Wrep[i] = 0ull;
    }
    const u64 bias2 = pack2(bias, bias);
    const u64 wih2  = pack2(wih, wih);

    if (lane < HID) hbuf[wip][0][lane] = make_float4(0.f, 0.f, 0.f, 0.f);
    __syncwarp();

    const float4* __restrict__ Xp = reinterpret_cast<const float4*>(X) + gw;
    float4* __restrict__       Yp = reinterpret_cast<float4*>(Y) + gw;
    const int stride4 = BATCH / 4;

    int cur = 0;
    for (int s = 0; s < SEQ; ++s) {
        float4 xs = Xp[s * stride4];     // uniform addr across warp -> 1 L1 request

        u64 acc0 = bias2, acc1 = bias2;
        #pragma unroll
        for (int i = 0; i < HID; i++) {
            float4 hv = hbuf[wip][cur][i];          // LDS.128 broadcast
            acc0 = fma2(pack2(hv.x, hv.y), Wrep[i], acc0);
            acc1 = fma2(pack2(hv.z, hv.w), Wrep[i], acc1);
        }
        acc0 = fma2(pack2(xs.x, xs.y), wih2, acc0); // wih=0 on lanes 30/31
        acc1 = fma2(pack2(xs.z, xs.w), wih2, acc1);

        float a0, a1, a2, a3;
        unpack2(acc0, a0, a1);
        unpack2(acc1, a2, a3);

        // Lane 30's accumulator consumed the state ENTERING step s, i.e. it is
        // y[s-1] = W_out·hs[s-1] + b_out. Store shifted by one.
        if (lane == HID && s > 0) {
            Yp[(s - 1) * stride4] = make_float4(a0, a1, a2, a3);
        }

        float t0 = fast_tanh(a0), t1 = fast_tanh(a1);
        float t2 = fast_tanh(a2), t3 = fast_tanh(a3);

        cur ^= 1;
        if (lane < HID) hbuf[wip][cur][lane] = make_float4(t0, t1, t2, t3);
        __syncwarp();
    }

    // Epilogue: one more matvec over the final state to produce y[SEQ-1].
    {
        u64 acc0 = bias2, acc1 = bias2;
        #pragma unroll
        for (int i = 0; i < HID; i++) {
            float4 hv = hbuf[wip][cur][i];
            acc0 = fma2(pack2(hv.x, hv.y), Wrep[i], acc0);
            acc1 = fma2(pack2(hv.z, hv.w), Wrep[i], acc1);
        }
        if (lane == HID) {
            float a0, a1, a2, a3;
            unpack2(acc0, a0, a1);
            unpack2(acc1, a2, a3);
            Yp[(SEQ - 1) * stride4] = make_float4(a0, a1, a2, a3);
        }
    }
}

extern "C" void kernel_launch(void* const* d_in, const int* in_sizes, int n_in,
                              void* d_out, int out_size) {
    const float* X     = (const float*)d_in[0];
    const float* W_ih  = (const float*)d_in[1];
    const float* W_hh  = (const float*)d_in[2];
    const float* b_ih  = (const float*)d_in[3];
    const float* b_hh  = (const float*)d_in[4];
    const float* W_out = (const float*)d_in[5];
    const float* b_out = (const float*)d_in[6];
    float* Y = (float*)d_out;

    rnn_tanh_kernel<<<BATCH / 16, 128>>>(X, W_ih, W_hh, b_ih, b_hh, W_out, b_out, Y);
}

// round 5
// speedup vs baseline: 1.2311x; 1.2311x over previous
#include <cuda_runtime.h>

// RNN: h_{s+1} = tanh(X[s]*W_ih^T + b_ih + b_hh + h_s @ W_hh^T); y_s = h_{s+1}·W_out + b_out
// SEQ=512, BATCH=4096, IN_DIM=1, HID=30.
//
// Latency-bound fix vs R4 (245us, occ=10.8%, issue=22.9%):
// - 2 batch elems per warp (one f32x2 acc) -> 2048 warps; 128 blocks x 512 thr
//   = exactly 16 warps/SM on 128 SMs = uniform 4 warps/SMSP (R4 had 1-2).
// - h state as packed u64 pairs in smem: LDS.64 feeds FFMA2 directly, no MOVs.
// - dot product split into 2 independent FMA chains (60cy vs 124cy critical path).
// - X prefetched 2 steps ahead as u64 (hides ~577cy DRAM latency).
// - lane 30 holds W_out/b_out -> readout y computed by the same matvec; its
//   accumulator at step s is y[s-1] (pre-state), stored shifted + epilogue.
// - tanh = 1 - 2/(ex2(2*log2e*x)+1): ~1e-6 err, proven 6.1e-7 end-to-end.

#define SEQ   512
#define BATCH 4096
#define HID   30

typedef unsigned long long u64;

__device__ __forceinline__ u64 pack2(float lo, float hi) {
    u64 r;
    asm("mov.b64 %0, {%1, %2};" : "=l"(r) : "f"(lo), "f"(hi));
    return r;
}
__device__ __forceinline__ void unpack2(u64 v, float& a, float& b) {
    asm("mov.b64 {%0, %1}, %2;" : "=f"(a), "=f"(b) : "l"(v));
}
__device__ __forceinline__ u64 fma2(u64 a, u64 b, u64 c) {
    u64 d;
    asm("fma.rn.f32x2 %0, %1, %2, %3;" : "=l"(d) : "l"(a), "l"(b), "l"(c));
    return d;
}
__device__ __forceinline__ u64 add2(u64 a, u64 b) {
    u64 d;
    asm("add.rn.f32x2 %0, %1, %2;" : "=l"(d) : "l"(a), "l"(b));
    return d;
}

__device__ __forceinline__ float fast_tanh(float x) {
    float t, r;
    asm("ex2.approx.f32 %0, %1;" : "=f"(t) : "f"(x * 2.8853900817779268f)); // 2*log2(e)
    asm("rcp.approx.f32 %0, %1;" : "=f"(r) : "f"(t + 1.0f));
    return __fmaf_rn(-2.0f, r, 1.0f);
}

__global__ void __launch_bounds__(512) rnn_tanh_kernel(
    const float* __restrict__ X,      // [SEQ, BATCH]
    const float* __restrict__ W_ih,   // [HID, 1]
    const float* __restrict__ W_hh,   // [HID, HID]
    const float* __restrict__ b_ih,   // [HID]
    const float* __restrict__ b_hh,   // [HID]
    const float* __restrict__ W_out,  // [1, HID]
    const float* __restrict__ b_out,  // [1]
    float* __restrict__ Y)            // [SEQ, BATCH]
{
    // 16 warps/block, each warp owns 2 batch elems (one f32x2 lane-pair).
    __shared__ u64 hbuf[16][2][32];   // [warp][buf][hid], packed pair

    const int lane = threadIdx.x & 31;
    const int wip  = threadIdx.x >> 5;             // 0..15
    const int gw   = blockIdx.x * 16 + wip;        // 0..2047; batch elems {2gw, 2gw+1}

    // Per-lane weight row replicated into both f32x2 halves.
    u64 Wrep[HID];
    float wih = 0.0f, bias = 0.0f;
    if (lane < HID) {
        #pragma unroll
        for (int i = 0; i < HID; i++) {
            float w = W_hh[lane * HID + i];
            Wrep[i] = pack2(w, w);
        }
        wih  = W_ih[lane];
        bias = b_ih[lane] + b_hh[lane];
    } else if (lane == HID) {
        #pragma unroll
        for (int i = 0; i < HID; i++) {
            float w = W_out[i];
            Wrep[i] = pack2(w, w);
        }
        bias = b_out[0];
    } else {
        #pragma unroll
        for (int i = 0; i < HID; i++) Wrep[i] = 0ull;
    }
    const u64 bias2 = pack2(bias, bias);
    const u64 wih2  = pack2(wih, wih);
    const u64 zero2 = 0ull;

    if (lane < HID) hbuf[wip][0][lane] = 0ull;
    __syncwarp();

    const u64* __restrict__ Xq = reinterpret_cast<const u64*>(X) + gw;  // pair per step
    u64* __restrict__       Yq = reinterpret_cast<u64*>(Y) + gw;
    const int ST = BATCH / 2;   // u64 elems per step row

    // X prefetch pipeline, depth 2.
    u64 x0 = Xq[0];
    u64 x1 = Xq[ST];

    int cur = 0;
    for (int s = 0; s < SEQ; ++s) {
        const u64 x_cur = x0;
        x0 = x1;
        if (s + 2 < SEQ) x1 = Xq[(s + 2) * ST];

        // Two independent FMA2 chains over the 30-term dot product.
        u64 acc_a = bias2, acc_b = zero2;
        #pragma unroll
        for (int i = 0; i < 15; i++) {
            acc_a = fma2(hbuf[wip][cur][2 * i],     Wrep[2 * i],     acc_a);
            acc_b = fma2(hbuf[wip][cur][2 * i + 1], Wrep[2 * i + 1], acc_b);
        }
        acc_b = fma2(x_cur, wih2, acc_b);          // wih=0 on lanes 30/31
        const u64 acc = add2(acc_a, acc_b);

        // Lane 30's acc consumed the state ENTERING step s -> it is y[s-1].
        if (lane == HID && s > 0) Yq[(s - 1) * ST] = acc;

        float a0, a1;
        unpack2(acc, a0, a1);
        const float t0 = fast_tanh(a0);
        const float t1 = fast_tanh(a1);

        cur ^= 1;
        if (lane < HID)
            *reinterpret_cast<float2*>(&hbuf[wip][cur][lane]) = make_float2(t0, t1);
        __syncwarp();
    }

    // Epilogue: final readout y[SEQ-1] from the last state.
    {
        u64 acc_a = bias2, acc_b = zero2;
        #pragma unroll
        for (int i = 0; i < 15; i++) {
            acc_a = fma2(hbuf[wip][cur][2 * i],     Wrep[2 * i],     acc_a);
            acc_b = fma2(hbuf[wip][cur][2 * i + 1], Wrep[2 * i + 1], acc_b);
        }
        if (lane == HID) Yq[(SEQ - 1) * ST] = add2(acc_a, acc_b);
    }
}

extern "C" void kernel_launch(void* const* d_in, const int* in_sizes, int n_in,
                              void* d_out, int out_size) {
    const float* X     = (const float*)d_in[0];
    const float* W_ih  = (const float*)d_in[1];
    const float* W_hh  = (const float*)d_in[2];
    const float* b_ih  = (const float*)d_in[3];
    const float* b_hh  = (const float*)d_in[4];
    const float* W_out = (const float*)d_in[5];
    const float* b_out = (const float*)d_in[6];
    float* Y = (float*)d_out;

    // 2048 warps / 16 warps per block = 128 blocks of 512 threads:
    // exactly one block per SM on 128 SMs, uniform 4 warps/SMSP.
    rnn_tanh_kernel<<<128, 512>>>(X, W_ih, W_hh, b_ih, b_hh, W_out, b_out, Y);
}